// round 2
// baseline (speedup 1.0000x reference)
#include <cuda_runtime.h>

// Soft quantizer forward value == hard nearest-level quantization.
// levels[k] = k * (2/24) - 1, k in [0, 24]. Nearest level of x:
//   k = clamp(rint((x + 1) * 12), 0, 24);  out = k * (2/24) - 1.
// Matches reference (soft_q + stop_grad(hard_q - soft_q) == hard_q in fwd)
// to ~1 ulp, far inside the 1e-3 rel-err threshold.

__device__ __forceinline__ float quant1(float x) {
    const float INV_STEP = 12.0f;            // (L-1)/(zmax-zmin)
    const float STEP     = 2.0f / 24.0f;     // same fp32 constant as reference
    float k = rintf(fmaf(x, INV_STEP, INV_STEP));   // (x+1)*12 as fma
    k = fminf(fmaxf(k, 0.0f), 24.0f);
    return fmaf(k, STEP, -1.0f);
}

__global__ void __launch_bounds__(256) quant_kernel(const float4* __restrict__ in,
                                                    float4* __restrict__ out,
                                                    int n4) {
    int i = blockIdx.x * blockDim.x + threadIdx.x;
    if (i < n4) {
        float4 v = in[i];
        float4 r;
        r.x = quant1(v.x);
        r.y = quant1(v.y);
        r.z = quant1(v.z);
        r.w = quant1(v.w);
        out[i] = r;
    }
}

// Tail handler for n not divisible by 4 (not needed for this shape, kept for safety).
__global__ void quant_tail(const float* __restrict__ in, float* __restrict__ out,
                           int start, int n) {
    int i = start + blockIdx.x * blockDim.x + threadIdx.x;
    if (i < n) out[i] = quant1(in[i]);
}

extern "C" void kernel_launch(void* const* d_in, const int* in_sizes, int n_in,
                              void* d_out, int out_size) {
    const float* x = (const float*)d_in[0];
    float* out = (float*)d_out;
    int n = out_size;
    int n4 = n / 4;
    if (n4 > 0) {
        int threads = 256;
        int blocks = (n4 + threads - 1) / threads;
        quant_kernel<<<blocks, threads>>>((const float4*)x, (float4*)out, n4);
    }
    int rem = n - n4 * 4;
    if (rem > 0) {
        quant_tail<<<1, 32>>>(x, out, n4 * 4, n);
    }
}

// round 3
// speedup vs baseline: 1.1628x; 1.1628x over previous
#include <cuda_runtime.h>

// Soft quantizer forward == hard nearest-level quantization (see R1 notes).
// R2: raise per-thread MLP — 4 independent LDG.128 front-batched per thread,
// streaming cache hints (data touched exactly once).

__device__ __forceinline__ float quant1(float x) {
    const float INV_STEP = 12.0f;
    const float STEP     = 2.0f / 24.0f;
    float k = rintf(fmaf(x, INV_STEP, INV_STEP));
    k = fminf(fmaxf(k, 0.0f), 24.0f);
    return fmaf(k, STEP, -1.0f);
}

__device__ __forceinline__ float4 quant4(float4 v) {
    float4 r;
    r.x = quant1(v.x);
    r.y = quant1(v.y);
    r.z = quant1(v.z);
    r.w = quant1(v.w);
    return r;
}

// Each thread handles VEC=4 float4s (64B load + 64B store), strided by
// blockDim so accesses within a batch stay fully coalesced per warp.
#define VEC 4

__global__ void __launch_bounds__(256) quant_kernel4(const float4* __restrict__ in,
                                                     float4* __restrict__ out,
                                                     int n4) {
    // Block b covers [b*256*VEC, b*256*VEC + 256*VEC) in float4 units,
    // thread t touches indices base + t + j*256 for j in [0,VEC).
    int base = blockIdx.x * (256 * VEC) + threadIdx.x;

    float4 v[VEC];
    // Front-batched independent loads (MLP_p1 = 4)
#pragma unroll
    for (int j = 0; j < VEC; j++) {
        int idx = base + j * 256;
        if (idx < n4) v[j] = __ldcs(&in[idx]);
    }
#pragma unroll
    for (int j = 0; j < VEC; j++) {
        int idx = base + j * 256;
        if (idx < n4) __stcs(&out[idx], quant4(v[j]));
    }
}

__global__ void quant_tail(const float* __restrict__ in, float* __restrict__ out,
                           int start, int n) {
    int i = start + blockIdx.x * blockDim.x + threadIdx.x;
    if (i < n) out[i] = quant1(in[i]);
}

extern "C" void kernel_launch(void* const* d_in, const int* in_sizes, int n_in,
                              void* d_out, int out_size) {
    const float* x = (const float*)d_in[0];
    float* out = (float*)d_out;
    int n = out_size;
    int n4 = n / 4;
    if (n4 > 0) {
        const int threads = 256;
        const int per_block = threads * VEC;
        int blocks = (n4 + per_block - 1) / per_block;
        quant_kernel4<<<blocks, threads>>>((const float4*)x, (float4*)out, n4);
    }
    int rem = n - n4 * 4;
    if (rem > 0) {
        quant_tail<<<1, 32>>>(x, out, n4 * 4, n);
    }
}

// round 5
// speedup vs baseline: 1.2048x; 1.0361x over previous
#include <cuda_runtime.h>

// Soft quantizer forward == hard nearest-level quantization (see R1 notes).
// R3: L2-residency play — input loaded with default caching (stays resident in
// 126MB L2 across graph replays), output stored evict-first (__stcs) so it
// never displaces the input. VEC=8 front-batched LDG.128, guard-free exact
// cover for n4 % (256*8) == 0.

__device__ __forceinline__ float quant1(float x) {
    const float INV_STEP = 12.0f;
    const float STEP     = 2.0f / 24.0f;
    float k = rintf(fmaf(x, INV_STEP, INV_STEP));
    k = fminf(fmaxf(k, 0.0f), 24.0f);
    return fmaf(k, STEP, -1.0f);
}

__device__ __forceinline__ float4 quant4(float4 v) {
    float4 r;
    r.x = quant1(v.x);
    r.y = quant1(v.y);
    r.z = quant1(v.z);
    r.w = quant1(v.w);
    return r;
}

#define VEC 8
#define TPB 256

// Exact-cover kernel: no bounds checks, grid*TPB*VEC == n4 exactly.
__global__ void __launch_bounds__(TPB) quant_kernel8(const float4* __restrict__ in,
                                                     float4* __restrict__ out) {
    int base = blockIdx.x * (TPB * VEC) + threadIdx.x;

    float4 v[VEC];
#pragma unroll
    for (int j = 0; j < VEC; j++)
        v[j] = in[base + j * TPB];          // default caching: keep in L2

#pragma unroll
    for (int j = 0; j < VEC; j++)
        __stcs(&out[base + j * TPB], quant4(v[j]));  // evict-first store
}

// Guarded fallback for shapes that don't divide evenly.
__global__ void __launch_bounds__(TPB) quant_kernel_g(const float4* __restrict__ in,
                                                      float4* __restrict__ out,
                                                      int n4, int start4) {
    int i = start4 + blockIdx.x * TPB + threadIdx.x;
    if (i < n4) __stcs(&out[i], quant4(in[i]));
}

__global__ void quant_tail(const float* __restrict__ in, float* __restrict__ out,
                           int start, int n) {
    int i = start + blockIdx.x * blockDim.x + threadIdx.x;
    if (i < n) out[i] = quant1(in[i]);
}

extern "C" void kernel_launch(void* const* d_in, const int* in_sizes, int n_in,
                              void* d_out, int out_size) {
    const float* x = (const float*)d_in[0];
    float* out = (float*)d_out;
    int n = out_size;
    int n4 = n / 4;

    const int per_block = TPB * VEC;
    int full_blocks = n4 / per_block;
    if (full_blocks > 0) {
        quant_kernel8<<<full_blocks, TPB>>>((const float4*)x, (float4*)out);
    }
    int done4 = full_blocks * per_block;
    int rem4 = n4 - done4;
    if (rem4 > 0) {
        quant_kernel_g<<<(rem4 + TPB - 1) / TPB, TPB>>>((const float4*)x, (float4*)out,
                                                        n4, done4);
    }
    int rem = n - n4 * 4;
    if (rem > 0) {
        quant_tail<<<1, 32>>>(x, out, n4 * 4, n);
    }
}